// round 12
// baseline (speedup 1.0000x reference)
#include <cuda_runtime.h>
#include <cuda_bf16.h>
#include <cstdint>

#define NN   50000
#define NPAD 50048          // 782 * 64
#define NE   400000
#define HID  128
#define NLAY 3
#define NG   512
#define EFS  12             // padded efeat stride (10 used)

#define WPAD 136            // padded row length (halves): ldmatrix conflict-free (272B stride)
#define WIMG_B (128*WPAD*2) // 34816 bytes per 128-row bf16 image
#define WMAT_B (2*WIMG_B)   // hi + lo per weight matrix = 69632
#define A_IMG_B (64*WPAD*2) // 17408 bytes per 64-row bf16 image
#define A_TOT_B (2*A_IMG_B) // 34816: A hi + lo
#define SMB (A_TOT_B + WMAT_B)  // 104448

// ---------------- scratch ----------------
__device__ float g_hn [NPAD*HID];
__device__ float g_q  [NPAD*HID];
__device__ float g_k  [NPAD*HID];
__device__ float g_v  [NPAD*HID];
__device__ float g_xr [NPAD*HID];
__device__ int   g_deg[NN];
__device__ int   g_rowptr[NN+1];
__device__ int   g_cursor[NN];
__device__ int   g_src [NE];        // CSR-ordered source node ids
__device__ float g_efeat [NE*EFS];  // edge order
__device__ float g_efeat2[NE*EFS];  // CSR order
__device__ float g_pooled[NG*HID];
__device__ __align__(128) char g_wimg[21*WMAT_B];

__device__ __forceinline__ float sp_f(float x){ return x > 20.f ? x : log1pf(expf(x)); }

__device__ __forceinline__ uint32_t smem_u32(const void* p){
    uint32_t a;
    asm("{ .reg .u64 t; cvta.to.shared.u64 t, %1; cvt.u32.u64 %0, t; }" : "=r"(a) : "l"(p));
    return a;
}
__device__ __forceinline__ void ldsm4(uint32_t addr, uint32_t* r){
    asm volatile("ldmatrix.sync.aligned.m8n8.x4.shared.b16 {%0,%1,%2,%3}, [%4];"
        : "=r"(r[0]), "=r"(r[1]), "=r"(r[2]), "=r"(r[3]) : "r"(addr));
}
__device__ __forceinline__ void mma16816(float* c, const uint32_t* a, uint32_t b0, uint32_t b1){
    asm volatile(
        "mma.sync.aligned.m16n8k16.row.col.f32.bf16.bf16.f32 "
        "{%0,%1,%2,%3}, {%4,%5,%6,%7}, {%8,%9}, {%0,%1,%2,%3};"
        : "+f"(c[0]), "+f"(c[1]), "+f"(c[2]), "+f"(c[3])
        : "r"(a[0]), "r"(a[1]), "r"(a[2]), "r"(a[3]), "r"(b0), "r"(b1));
}
__device__ __forceinline__ void cp16(uint32_t saddr, const void* gptr){
    asm volatile("cp.async.cg.shared.global [%0], [%1], 16;" :: "r"(saddr), "l"(gptr));
}
#define CP_COMMIT() asm volatile("cp.async.commit_group;" ::: "memory")
#define CP_WAIT(n)  asm volatile("cp.async.wait_group %0;" :: "n"(n) : "memory")

// ---------------- init: LN(h0) -> g_hn; zero deg/cursor ----------------
__global__ void k_init_ln(const float* __restrict__ h,
                          const float* __restrict__ gam, const float* __restrict__ bet){
    int n = blockIdx.x*4 + (threadIdx.x>>5);
    if(n >= NPAD) return;
    int lane = threadIdx.x & 31;
    if(n < NN && lane == 0){ g_deg[n] = 0; g_cursor[n] = 0; }
    if(n >= NN){ ((float4*)g_hn)[n*32+lane] = make_float4(0.f,0.f,0.f,0.f); return; }
    float4 x = ((const float4*)h)[n*32 + lane];
    float s  = x.x+x.y+x.z+x.w;
    float ss = x.x*x.x+x.y*x.y+x.z*x.z+x.w*x.w;
    #pragma unroll
    for(int o=16;o;o>>=1){
        s  += __shfl_xor_sync(0xffffffffu, s,  o);
        ss += __shfl_xor_sync(0xffffffffu, ss, o);
    }
    float mean = s*(1.f/128.f);
    float var  = ss*(1.f/128.f) - mean*mean;
    float inv  = rsqrtf(var + 1e-5f);
    float4 g4 = ((const float4*)gam)[lane];
    float4 b4 = ((const float4*)bet)[lane];
    float4 y;
    y.x=(x.x-mean)*inv*g4.x+b4.x;
    y.y=(x.y-mean)*inv*g4.y+b4.y;
    y.z=(x.z-mean)*inv*g4.z+b4.z;
    y.w=(x.w-mean)*inv*g4.w+b4.w;
    ((float4*)g_hn)[n*32 + lane] = y;
}

// ---------------- combined prep ----------------
__global__ void k_prep_all(const float* Wq, const float* Wk, const float* Wv, const float* Ws,
                           const float* W1, const float* W2, const float* W3,
                           const float* __restrict__ pos, const float* __restrict__ ew,
                           const int* __restrict__ ei){
    int idx = blockIdx.x*256 + threadIdx.x;
    if(idx < 21*16384){
        int m = idx >> 14;
        int within = idx & 16383;
        int n = within >> 7, k2 = within & 127;
        int fam = m/3, layer = m - fam*3;
        const float* W;
        switch(fam){
            case 0: W = Wq; break; case 1: W = Wk; break; case 2: W = Wv; break;
            case 3: W = Ws; break; case 4: W = W1; break; case 5: W = W2; break;
            default: W = W3; break;
        }
        float w = W[layer*16384 + k2*128 + n];
        __nv_bfloat16 hi = __float2bfloat16(w);
        __nv_bfloat16 lo = __float2bfloat16(w - __bfloat162float(hi));
        char* base = g_wimg + (size_t)m*WMAT_B;
        int off = (n*WPAD + k2)*2;
        *(__nv_bfloat16*)(base + off) = hi;
        *(__nv_bfloat16*)(base + WIMG_B + off) = lo;
    }
    if(idx < NG*HID) g_pooled[idx] = 0.f;
    if(idx < NE){
        int e = idx;
        int s = ei[e], d = ei[NE+e];
        atomicAdd(&g_deg[d], 1);
        float dx = pos[d*3+0]-pos[s*3+0];
        float dy = pos[d*3+1]-pos[s*3+1];
        float dz = pos[d*3+2]-pos[s*3+2];
        float D  = sqrtf(dx*dx+dy*dy+dz*dz);
        float x  = D*0.1f;
        float cut = 0.f;
        if(x < 1.f){
            float x3=x*x*x, x4=x3*x, x5=x4*x;
            cut = 1.f - 6.f*x5 + 15.f*x4 - 10.f*x3;
        }
        float ed = expf(-D);
        const float cK = expf(-10.f);
        const float dc = (cK - 1.f)/8.f;
        float w = 4.5f/(1.f - cK); w = w*w;
        #pragma unroll
        for(int r=0;r<9;r++){
            float c = 1.f + (float)r*dc;
            float t = ed - c;
            g_efeat[e*EFS+r] = cut * expf(-w*t*t);
        }
        g_efeat[e*EFS+9]  = ew[e];
        g_efeat[e*EFS+10] = 0.f;
        g_efeat[e*EFS+11] = 0.f;
    }
}

// ---------------- shared GEMM pieces (256 threads, 8 warps: 4 M x 2 N; 64-row tiles) ----------------
__device__ __forceinline__ void stage_A64(char* smem, const float* __restrict__ A, int row0, int tid){
    const float4* A4 = (const float4*)A;
    #pragma unroll
    for(int j=0;j<8;j++){
        int idx = j*256 + tid;
        int row = idx >> 5;
        int c4  = (idx & 31) << 2;
        float4 a = A4[(size_t)(row0+row)*32 + (idx&31)];
        __nv_bfloat16 h0=__float2bfloat16(a.x), h1=__float2bfloat16(a.y);
        __nv_bfloat16 h2=__float2bfloat16(a.z), h3=__float2bfloat16(a.w);
        __nv_bfloat16 l0=__float2bfloat16(a.x-__bfloat162float(h0));
        __nv_bfloat16 l1=__float2bfloat16(a.y-__bfloat162float(h1));
        __nv_bfloat16 l2=__float2bfloat16(a.z-__bfloat162float(h2));
        __nv_bfloat16 l3=__float2bfloat16(a.w-__bfloat162float(h3));
        int off = (row*WPAD + c4)*2;
        *(__nv_bfloat162*)(smem + off  )           = __nv_bfloat162(h0,h1);
        *(__nv_bfloat162*)(smem + off+4)           = __nv_bfloat162(h2,h3);
        *(__nv_bfloat162*)(smem + A_IMG_B + off  ) = __nv_bfloat162(l0,l1);
        *(__nv_bfloat162*)(smem + A_IMG_B + off+4) = __nv_bfloat162(l2,l3);
    }
}
__device__ __forceinline__ void prefetch_W(uint32_t sbW, const char* __restrict__ wsrc, int tid){
    #pragma unroll
    for(int j=0;j<17;j++){
        int c = j*256 + tid;
        if(c < WMAT_B/16) cp16(sbW + c*16, wsrc + c*16);
    }
}
__device__ __forceinline__ void mma_tile64(uint32_t sbA, uint32_t sbW, float* acc, int wm, int wn, int lane){
    int i4 = lane>>3, r8 = lane&7;
    int a_row = wm*16 + r8 + (i4&1)*8;
    int a_col = (i4>>1)*8;
    int b_row = wn*64 + (i4>>1)*8 + r8;
    int b_col = (i4&1)*8;
    #pragma unroll
    for(int ks=0; ks<8; ks++){
        int k0 = ks*16;
        uint32_t aoff = (uint32_t)(a_row*WPAD + k0 + a_col)*2;
        uint32_t ahi[4], alo[4];
        ldsm4(sbA + aoff, ahi);
        ldsm4(sbA + A_IMG_B + aoff, alo);
        #pragma unroll
        for(int p=0;p<4;p++){
            uint32_t boff = (uint32_t)((b_row + p*16)*WPAD + k0 + b_col)*2;
            uint32_t bh[4], bl[4];
            ldsm4(sbW + boff, bh);
            ldsm4(sbW + WIMG_B + boff, bl);
            float* c0 = acc + p*8;
            float* c1 = acc + p*8 + 4;
            mma16816(c0, ahi, bh[0], bh[1]);
            mma16816(c1, ahi, bh[2], bh[3]);
            mma16816(c0, ahi, bl[0], bl[1]);
            mma16816(c1, ahi, bl[2], bl[3]);
            mma16816(c0, alo, bh[0], bh[1]);
            mma16816(c1, alo, bh[2], bh[3]);
        }
    }
}
__device__ __forceinline__ void epilogue_plain64(const float* acc, const float* __restrict__ bias,
                                                 float* __restrict__ out, int row0, int wm, int wn,
                                                 int lane){
    int rA = row0 + wm*16 + (lane>>2);
    int rB = rA + 8;
    #pragma unroll
    for(int f=0; f<8; f++){
        int idx = (f>>1)*8 + (f&1)*4;
        int col0 = wn*64 + f*8 + 2*(lane&3);
        float b0 = __ldg(bias + col0), b1 = __ldg(bias + col0 + 1);
        *(float2*)(out + (size_t)rA*HID + col0) = make_float2(acc[idx+0]+b0, acc[idx+1]+b1);
        *(float2*)(out + (size_t)rB*HID + col0) = make_float2(acc[idx+2]+b0, acc[idx+3]+b1);
    }
}
__device__ __forceinline__ void frag_to_img64(char* smem, const float* acc, const float* __restrict__ bias,
                                              int wm, int wn, int lane){
    int rA = wm*16 + (lane>>2);
    int rB = rA + 8;
    #pragma unroll
    for(int f=0; f<8; f++){
        int idx = (f>>1)*8 + (f&1)*4;
        int col0 = wn*64 + f*8 + 2*(lane&3);
        float b0 = __ldg(bias + col0), b1 = __ldg(bias + col0 + 1);
        float v0 = sp_f(acc[idx+0]+b0), v1 = sp_f(acc[idx+1]+b1);
        float v2 = sp_f(acc[idx+2]+b0), v3 = sp_f(acc[idx+3]+b1);
        __nv_bfloat16 h0=__float2bfloat16(v0), h1=__float2bfloat16(v1);
        __nv_bfloat16 h2=__float2bfloat16(v2), h3=__float2bfloat16(v3);
        __nv_bfloat16 l0=__float2bfloat16(v0-__bfloat162float(h0));
        __nv_bfloat16 l1=__float2bfloat16(v1-__bfloat162float(h1));
        __nv_bfloat16 l2=__float2bfloat16(v2-__bfloat162float(h2));
        __nv_bfloat16 l3=__float2bfloat16(v3-__bfloat162float(h3));
        int oA = (rA*WPAD + col0)*2, oB = (rB*WPAD + col0)*2;
        *(__nv_bfloat162*)(smem + oA)           = __nv_bfloat162(h0,h1);
        *(__nv_bfloat162*)(smem + A_IMG_B + oA) = __nv_bfloat162(l0,l1);
        *(__nv_bfloat162*)(smem + oB)           = __nv_bfloat162(h2,h3);
        *(__nv_bfloat162*)(smem + A_IMG_B + oB) = __nv_bfloat162(l2,l3);
    }
}

// ---------------- fused QKVS GEMM ----------------
__global__ void __launch_bounds__(256) k_gemm4(
        const float* __restrict__ A, const char* __restrict__ wimg, int layer,
        const float* __restrict__ bq, const float* __restrict__ bk,
        const float* __restrict__ bv, const float* __restrict__ bs,
        float* __restrict__ oq, float* __restrict__ ok,
        float* __restrict__ ov, float* __restrict__ oxr){
    extern __shared__ __align__(16) char smem[];
    uint32_t sb = smem_u32(smem);
    int tid = threadIdx.x, wid = tid>>5, lane = tid&31;
    int wm = wid & 3, wn = wid >> 2;
    int row0 = blockIdx.x*64;
    const uint32_t sbA = sb;
    const uint32_t sbW = sb + A_TOT_B;

    prefetch_W(sbW, wimg + (size_t)(0*3 + layer)*WMAT_B, tid);
    CP_COMMIT();
    stage_A64(smem, A, row0, tid);

    const float* biases[4] = {bq + layer*HID, bk + layer*HID, bv + layer*HID, bs + layer*HID};
    float* outs[4] = {oq, ok, ov, oxr};

    #pragma unroll
    for(int m=0;m<4;m++){
        CP_WAIT(0);
        __syncthreads();
        float acc[32];
        #pragma unroll
        for(int i=0;i<32;i++) acc[i]=0.f;
        mma_tile64(sbA, sbW, acc, wm, wn, lane);
        __syncthreads();
        if(m<3){
            prefetch_W(sbW, wimg + (size_t)((m+1)*3 + layer)*WMAT_B, tid);
            CP_COMMIT();
        }
        epilogue_plain64(acc, biases[m], outs[m], row0, wm, wn, lane);
    }
}

// ---------------- fused FFN ----------------
template<int MODE>
__global__ void __launch_bounds__(256) k_ffn(
        const char* __restrict__ wimg, int layer,
        const float* __restrict__ b1, const float* __restrict__ b2, const float* __restrict__ b3,
        const float* __restrict__ gam, const float* __restrict__ bet,
        const int* __restrict__ batch){
    extern __shared__ __align__(16) char smem[];
    uint32_t sb = smem_u32(smem);
    int tid = threadIdx.x, wid = tid>>5, lane = tid&31;
    int wm = wid & 3, wn = wid >> 2;
    int row0 = blockIdx.x*64;
    const uint32_t sbA = sb;
    const uint32_t sbW = sb + A_TOT_B;
    const float* bias1 = b1 + layer*HID;
    const float* bias2 = b2 + layer*HID;
    const float* bias3 = b3 + layer*HID;

    prefetch_W(sbW, wimg + (size_t)(4*3 + layer)*WMAT_B, tid);  // W1
    CP_COMMIT();
    stage_A64(smem, g_hn, row0, tid);
    CP_WAIT(0);
    __syncthreads();

    float acc[32];
    #pragma unroll
    for(int i=0;i<32;i++) acc[i]=0.f;
    mma_tile64(sbA, sbW, acc, wm, wn, lane);         // GEMM1
    __syncthreads();
    prefetch_W(sbW, wimg + (size_t)(5*3 + layer)*WMAT_B, tid);  // W2
    CP_COMMIT();
    frag_to_img64(smem, acc, bias1, wm, wn, lane);
    CP_WAIT(0);
    __syncthreads();

    #pragma unroll
    for(int i=0;i<32;i++) acc[i]=0.f;
    mma_tile64(sbA, sbW, acc, wm, wn, lane);         // GEMM2
    __syncthreads();
    prefetch_W(sbW, wimg + (size_t)(6*3 + layer)*WMAT_B, tid);  // W3
    CP_COMMIT();
    frag_to_img64(smem, acc, bias2, wm, wn, lane);
    CP_WAIT(0);
    __syncthreads();

    #pragma unroll
    for(int i=0;i<32;i++) acc[i]=0.f;
    mma_tile64(sbA, sbW, acc, wm, wn, lane);         // GEMM3
    __syncthreads();

    float* stage = (float*)smem;
    {
        int rA = wm*16 + (lane>>2);
        int rB = rA + 8;
        #pragma unroll
        for(int f=0; f<8; f++){
            int idx = (f>>1)*8 + (f&1)*4;
            int col0 = wn*64 + f*8 + 2*(lane&3);
            float b0 = __ldg(bias3 + col0), c1 = __ldg(bias3 + col0 + 1);
            float v0 = sp_f(acc[idx+0]+b0), v1 = sp_f(acc[idx+1]+c1);
            float v2 = sp_f(acc[idx+2]+b0), v3 = sp_f(acc[idx+3]+c1);
            const float2 r0 = *(const float2*)(g_hn + (size_t)(row0+rA)*HID + col0);
            const float2 r1 = *(const float2*)(g_hn + (size_t)(row0+rB)*HID + col0);
            stage[rA*129 + col0] = v0 + r0.x; stage[rA*129 + col0+1] = v1 + r0.y;
            stage[rB*129 + col0] = v2 + r1.x; stage[rB*129 + col0+1] = v3 + r1.y;
        }
    }
    __syncthreads();
    for(int r=wid; r<64; r+=8){
        float4 x;
        x.x = stage[r*129 + lane*4 + 0];
        x.y = stage[r*129 + lane*4 + 1];
        x.z = stage[r*129 + lane*4 + 2];
        x.w = stage[r*129 + lane*4 + 3];
        if(MODE == 1){
            float s  = x.x+x.y+x.z+x.w;
            float ss = x.x*x.x+x.y*x.y+x.z*x.z+x.w*x.w;
            #pragma unroll
            for(int o=16;o;o>>=1){
                s  += __shfl_xor_sync(0xffffffffu, s,  o);
                ss += __shfl_xor_sync(0xffffffffu, ss, o);
            }
            float mean = s*(1.f/128.f);
            float var  = ss*(1.f/128.f) - mean*mean;
            float inv  = rsqrtf(var + 1e-5f);
            float4 g4 = ((const float4*)gam)[lane];
            float4 b4 = ((const float4*)bet)[lane];
            float4 y;
            y.x=(x.x-mean)*inv*g4.x+b4.x;
            y.y=(x.y-mean)*inv*g4.y+b4.y;
            y.z=(x.z-mean)*inv*g4.z+b4.z;
            y.w=(x.w-mean)*inv*g4.w+b4.w;
            ((float4*)g_hn)[(size_t)(row0+r)*32 + lane] = y;
        } else {
            int gr = row0 + r;
            if(gr < NN){
                int g = batch[gr];
                float* base = &g_pooled[g*HID + 4*lane];
                atomicAdd(base+0, x.x); atomicAdd(base+1, x.y);
                atomicAdd(base+2, x.z); atomicAdd(base+3, x.w);
            }
        }
    }
}

// ---------------- CSR scan + scatter ----------------
__global__ void k_scan(){
    __shared__ int wtot[32];
    __shared__ int carry;
    int tid = threadIdx.x, lane = tid & 31, wid = tid >> 5;
    if(tid==0) carry = 0;
    __syncthreads();
    for(int base=0; base<NN; base+=1024){
        int i = base + tid;
        int v = (i < NN) ? g_deg[i] : 0;
        int s = v;
        #pragma unroll
        for(int o=1;o<32;o<<=1){
            int t = __shfl_up_sync(0xffffffffu, s, o);
            if(lane >= o) s += t;
        }
        if(lane==31) wtot[wid] = s;
        __syncthreads();
        if(wid==0){
            int t = wtot[lane];
            int u = t;
            #pragma unroll
            for(int o=1;o<32;o<<=1){
                int tt = __shfl_up_sync(0xffffffffu, u, o);
                if(lane >= o) u += tt;
            }
            wtot[lane] = u;
        }
        __syncthreads();
        int off = carry + (wid>0 ? wtot[wid-1] : 0);
        if(i < NN) g_rowptr[i] = off + s - v;
        int tot = wtot[31];
        __syncthreads();
        if(tid==0) carry += tot;
        __syncthreads();
    }
    if(tid==0) g_rowptr[NN] = carry;
}
__global__ void k_scatter(const int* __restrict__ ei){
    int e = blockIdx.x*256 + threadIdx.x;
    if(e >= NE) return;
    int d = ei[NE+e];
    int p = g_rowptr[d] + atomicAdd(&g_cursor[d], 1);
    g_src[p] = ei[e];
    const float4* s4 = (const float4*)(g_efeat + (size_t)e*EFS);
    float4* d4 = (float4*)(g_efeat2 + (size_t)p*EFS);
    d4[0] = s4[0]; d4[1] = s4[1]; d4[2] = s4[2];
}

// ---------------- fused single-pass attention: logits + online softmax + aggregate + gate + LN ----------------
__global__ void __launch_bounds__(256) k_attn(const float* __restrict__ We,
                       const float* __restrict__ Wb,
                       const float* __restrict__ gam, const float* __restrict__ bet){
    int n = blockIdx.x*8 + (threadIdx.x>>5);
    if(n >= NN) return;
    int lane = threadIdx.x & 31;
    int row = g_rowptr[n];
    int deg = g_rowptr[n+1] - row;

    float4 q4 = __ldg(((const float4*)g_q) + (size_t)n*32 + lane);

    // t_r = q . We_r (per head; reduce over the 8 lanes of this head)
    float t[10];
    #pragma unroll
    for(int r=0;r<10;r++){
        float4 w4 = __ldg(((const float4*)We) + r*32 + lane);
        float d = q4.x*w4.x + q4.y*w4.y + q4.z*w4.z + q4.w*w4.w;
        d += __shfl_xor_sync(0xffffffffu, d, 1);
        d += __shfl_xor_sync(0xffffffffu, d, 2);
        d += __shfl_xor_sync(0xffffffffu, d, 4);
        t[r] = d;
    }

    // single pass: online softmax + aggregation
    const float SC = 0.17677669529663687f; // 1/sqrt(32)
    float m = -1e30f, ssum = 0.f;
    float4 accv = make_float4(0.f,0.f,0.f,0.f);
    float4 A0 = make_float4(0.f,0.f,0.f,0.f);
    float4 A1 = make_float4(0.f,0.f,0.f,0.f);
    float2 A2 = make_float2(0.f,0.f);
    for(int i=0;i<deg;i++){
        size_t p = row + i;
        int s = __ldg(&g_src[p]);
        float4 k4 = __ldg(((const float4*)g_k) + (size_t)s*32 + lane);
        float4 v4 = __ldg(((const float4*)g_v) + (size_t)s*32 + lane);
        float4 ef0 = __ldg((const float4*)(g_efeat2 + p*EFS));
        float4 ef1 = __ldg((const float4*)(g_efeat2 + p*EFS + 4));
        float2 ef2 = __ldg((const float2*)(g_efeat2 + p*EFS + 8));
        float pq = q4.x*k4.x + q4.y*k4.y + q4.z*k4.z + q4.w*k4.w;
        pq += __shfl_xor_sync(0xffffffffu, pq, 1);
        pq += __shfl_xor_sync(0xffffffffu, pq, 2);
        pq += __shfl_xor_sync(0xffffffffu, pq, 4);
        float l = (pq
                 + t[0]*ef0.x + t[1]*ef0.y + t[2]*ef0.z + t[3]*ef0.w
                 + t[4]*ef1.x + t[5]*ef1.y + t[6]*ef1.z + t[7]*ef1.w
                 + t[8]*ef2.x + t[9]*ef2.y) * SC;
        float mn = fmaxf(m, l);
        float c  = expf(m - mn);     // first iter: exp(-inf) = 0
        float w  = expf(l - mn);
        m = mn;
        ssum = ssum*c + w;
        accv.x = accv.x*c + w*v4.x; accv.y = accv.y*c + w*v4.y;
        accv.z = accv.z*c + w*v4.z; accv.w = accv.w*c + w*v4.w;
        A0.x = A0.x*c + w*ef0.x; A0.y = A0.y*c + w*ef0.y;
        A0.z = A0.z*c + w*ef0.z; A0.w = A0.w*c + w*ef0.w;
        A1.x = A1.x*c + w*ef1.x; A1.y = A1.y*c + w*ef1.y;
        A1.z = A1.z*c + w*ef1.z; A1.w = A1.w*c + w*ef1.w;
        A2.x = A2.x*c + w*ef2.x; A2.y = A2.y*c + w*ef2.y;
    }
    // add (sum_e a*efeat) @ We
    {
        float Ar[10] = {A0.x,A0.y,A0.z,A0.w,A1.x,A1.y,A1.z,A1.w,A2.x,A2.y};
        #pragma unroll
        for(int r=0;r<10;r++){
            float4 w4 = __ldg(((const float4*)We) + r*32 + lane);
            accv.x += Ar[r]*w4.x; accv.y += Ar[r]*w4.y;
            accv.z += Ar[r]*w4.z; accv.w += Ar[r]*w4.w;
        }
    }
    float inv = (deg>0) ? 1.f/ssum : 0.f;
    float4 o; o.x=accv.x*inv; o.y=accv.y*inv; o.z=accv.z*inv; o.w=accv.w*inv;

    // beta gate + softplus residual
    float4 x  = ((const float4*)g_xr)[(size_t)n*32+lane];
    float4 hn = ((const float4*)g_hn)[(size_t)n*32+lane];
    float4 w0 = ((const float4*)Wb)[lane];
    float4 w1 = ((const float4*)Wb)[32+lane];
    float4 w2 = ((const float4*)Wb)[64+lane];
    float pb = o.x*w0.x + o.y*w0.y + o.z*w0.z + o.w*w0.w
             + x.x*w1.x + x.y*w1.y + x.z*w1.z + x.w*w1.w
             + (o.x-x.x)*w2.x + (o.y-x.y)*w2.y + (o.z-x.z)*w2.z + (o.w-x.w)*w2.w;
    #pragma unroll
    for(int off=16;off;off>>=1) pb += __shfl_xor_sync(0xffffffffu, pb, off);
    float beta = 1.f/(1.f+expf(-pb));
    float4 r;
    r.x = beta*x.x + (1.f-beta)*o.x;
    r.y = beta*x.y + (1.f-beta)*o.y;
    r.z = beta*x.z + (1.f-beta)*o.z;
    r.w = beta*x.w + (1.f-beta)*o.w;
    float4 hv;
    hv.x = hn.x + sp_f(r.x); hv.y = hn.y + sp_f(r.y);
    hv.z = hn.z + sp_f(r.z); hv.w = hn.w + sp_f(r.w);

    // fused LN -> g_hn
    float s  = hv.x+hv.y+hv.z+hv.w;
    float ss = hv.x*hv.x+hv.y*hv.y+hv.z*hv.z+hv.w*hv.w;
    #pragma unroll
    for(int off=16;off;off>>=1){
        s  += __shfl_xor_sync(0xffffffffu, s,  off);
        ss += __shfl_xor_sync(0xffffffffu, ss, off);
    }
    float mean = s*(1.f/128.f);
    float var  = ss*(1.f/128.f) - mean*mean;
    float invs = rsqrtf(var + 1e-5f);
    float4 g4 = ((const float4*)gam)[lane];
    float4 b4 = ((const float4*)bet)[lane];
    float4 y;
    y.x=(hv.x-mean)*invs*g4.x+b4.x;
    y.y=(hv.y-mean)*invs*g4.y+b4.y;
    y.z=(hv.z-mean)*invs*g4.z+b4.z;
    y.w=(hv.w-mean)*invs*g4.w+b4.w;
    ((float4*)g_hn)[(size_t)n*32+lane] = y;
}

// ---------------- readout head ----------------
__global__ void k_final(const float* __restrict__ Wo1, const float* __restrict__ bo1,
                        const float* __restrict__ Wo2, const float* __restrict__ bo2,
                        float* __restrict__ out){
    int g = blockIdx.x*4 + (threadIdx.x>>5);
    if(g >= NG) return;
    int lane = threadIdx.x & 31;
    float4 acc = ((const float4*)bo1)[lane];
    const float* p = &g_pooled[g*HID];
    for(int k2=0;k2<HID;k2++){
        float a = p[k2];
        float4 w = __ldg(((const float4*)Wo1) + k2*32 + lane);
        acc.x += a*w.x; acc.y += a*w.y; acc.z += a*w.z; acc.w += a*w.w;
    }
    float4 w2 = ((const float4*)Wo2)[lane];
    float r = sp_f(acc.x)*w2.x + sp_f(acc.y)*w2.y + sp_f(acc.z)*w2.z + sp_f(acc.w)*w2.w;
    #pragma unroll
    for(int off=16;off;off>>=1) r += __shfl_xor_sync(0xffffffffu, r, off);
    if(lane==0) out[g] = r + bo2[0];
}

// ---------------- driver ----------------
extern "C" void kernel_launch(void* const* d_in, const int* in_sizes, int n_in,
                              void* d_out, int out_size){
    const float* h   = (const float*)d_in[0];
    const float* pos = (const float*)d_in[1];
    const float* ew  = (const float*)d_in[2];
    const float* Wq  = (const float*)d_in[3];  const float* bq = (const float*)d_in[4];
    const float* Wk  = (const float*)d_in[5];  const float* bk = (const float*)d_in[6];
    const float* Wv  = (const float*)d_in[7];  const float* bv = (const float*)d_in[8];
    const float* We  = (const float*)d_in[9];
    const float* Ws  = (const float*)d_in[10]; const float* bs = (const float*)d_in[11];
    const float* Wb  = (const float*)d_in[12];
    const float* W1  = (const float*)d_in[13]; const float* b1 = (const float*)d_in[14];
    const float* W2  = (const float*)d_in[15]; const float* b2 = (const float*)d_in[16];
    const float* W3  = (const float*)d_in[17]; const float* b3 = (const float*)d_in[18];
    const float* lgm = (const float*)d_in[19]; const float* lbt = (const float*)d_in[20];
    const float* Wo1 = (const float*)d_in[21]; const float* bo1 = (const float*)d_in[22];
    const float* Wo2 = (const float*)d_in[23]; const float* bo2 = (const float*)d_in[24];
    const int*   ei  = (const int*)d_in[25];
    const int*   bat = (const int*)d_in[26];
    float* out = (float*)d_out;

    float *p_hn,*p_q,*p_k,*p_v,*p_xr;
    char* p_wimg;
    cudaGetSymbolAddress((void**)&p_hn, g_hn);
    cudaGetSymbolAddress((void**)&p_q,  g_q);
    cudaGetSymbolAddress((void**)&p_k,  g_k);
    cudaGetSymbolAddress((void**)&p_v,  g_v);
    cudaGetSymbolAddress((void**)&p_xr, g_xr);
    cudaGetSymbolAddress((void**)&p_wimg, g_wimg);

    cudaFuncSetAttribute(k_gemm4,   cudaFuncAttributeMaxDynamicSharedMemorySize, SMB);
    cudaFuncSetAttribute(k_ffn<1>,  cudaFuncAttributeMaxDynamicSharedMemorySize, SMB);
    cudaFuncSetAttribute(k_ffn<2>,  cudaFuncAttributeMaxDynamicSharedMemorySize, SMB);

    const int NB = NPAD/64; // 782

    k_init_ln <<<NPAD/4, 128>>>(h, lgm, lbt);                                    // 0
    k_prep_all<<<(NE+255)/256, 256>>>(Wq,Wk,Wv,Ws,W1,W2,W3, pos, ew, ei);        // 1
    k_scan    <<<1, 1024>>>();                                                   // 2
    k_gemm4   <<<NB, 256, SMB>>>(p_hn, p_wimg, 0, bq, bk, bv, bs,                // 3 <- profiled
                                 p_q, p_k, p_v, p_xr);
    k_scatter <<<(NE+255)/256, 256>>>(ei);                                       // 4

    for(int i=0;i<NLAY;i++){
        const float* Wei=We+i*10*HID;
        const float* Wbi=Wb+i*3*HID;
        if(i>0)
            k_gemm4 <<<NB, 256, SMB>>>(p_hn, p_wimg, i, bq, bk, bv, bs, p_q, p_k, p_v, p_xr);
        k_attn<<<(NN+7)/8, 256>>>(Wei, Wbi, lgm, lbt);
        if(i < NLAY-1)
            k_ffn<1><<<NB, 256, SMB>>>(p_wimg, i, b1, b2, b3, lgm, lbt, nullptr);
        else
            k_ffn<2><<<NB, 256, SMB>>>(p_wimg, i, b1, b2, b3, nullptr, nullptr, bat);
    }

    k_final<<<NG/4, 128>>>(Wo1, bo1, Wo2, bo2, out);
}

// round 13
// speedup vs baseline: 1.3210x; 1.3210x over previous
#include <cuda_runtime.h>
#include <cuda_bf16.h>
#include <cstdint>

#define NN   50000
#define NPAD 50048          // 782 * 64
#define NE   400000
#define HID  128
#define NLAY 3
#define NG   512
#define EFS  12             // padded efeat stride (10 used)

#define WPAD 136            // padded row length (halves): ldmatrix conflict-free (272B stride)
#define WIMG_B (128*WPAD*2) // 34816 bytes per 128-row bf16 image
#define WMAT_B (2*WIMG_B)   // hi + lo per weight matrix = 69632
#define A_IMG_B (64*WPAD*2) // 17408 bytes per 64-row bf16 image
#define A_TOT_B (2*A_IMG_B) // 34816: A hi + lo
#define SMB (A_TOT_B + WMAT_B)  // 104448

// ---------------- scratch ----------------
__device__ float g_hn [NPAD*HID];
__device__ float g_q  [NPAD*HID];
__device__ float g_k  [NPAD*HID];
__device__ float g_v  [NPAD*HID];
__device__ float g_xr [NPAD*HID];
__device__ float g_w  [NE*4];       // logits, CSR position order
__device__ int   g_deg[NN];
__device__ int   g_rowptr[NN+1];
__device__ int   g_cursor[NN];
__device__ int   g_src [NE];        // CSR-ordered source node ids
__device__ int   g_dst [NE];        // CSR-ordered destination node ids (monotone)
__device__ float g_efeat [NE*EFS];  // edge order
__device__ float g_efeat2[NE*EFS];  // CSR order
__device__ float g_pooled[NG*HID];
__device__ __align__(128) char g_wimg[21*WMAT_B];

__device__ __forceinline__ float sp_f(float x){ return x > 20.f ? x : log1pf(expf(x)); }

__device__ __forceinline__ uint32_t smem_u32(const void* p){
    uint32_t a;
    asm("{ .reg .u64 t; cvta.to.shared.u64 t, %1; cvt.u32.u64 %0, t; }" : "=r"(a) : "l"(p));
    return a;
}
__device__ __forceinline__ void ldsm4(uint32_t addr, uint32_t* r){
    asm volatile("ldmatrix.sync.aligned.m8n8.x4.shared.b16 {%0,%1,%2,%3}, [%4];"
        : "=r"(r[0]), "=r"(r[1]), "=r"(r[2]), "=r"(r[3]) : "r"(addr));
}
__device__ __forceinline__ void mma16816(float* c, const uint32_t* a, uint32_t b0, uint32_t b1){
    asm volatile(
        "mma.sync.aligned.m16n8k16.row.col.f32.bf16.bf16.f32 "
        "{%0,%1,%2,%3}, {%4,%5,%6,%7}, {%8,%9}, {%0,%1,%2,%3};"
        : "+f"(c[0]), "+f"(c[1]), "+f"(c[2]), "+f"(c[3])
        : "r"(a[0]), "r"(a[1]), "r"(a[2]), "r"(a[3]), "r"(b0), "r"(b1));
}
__device__ __forceinline__ void cp16(uint32_t saddr, const void* gptr){
    asm volatile("cp.async.cg.shared.global [%0], [%1], 16;" :: "r"(saddr), "l"(gptr));
}
#define CP_COMMIT() asm volatile("cp.async.commit_group;" ::: "memory")
#define CP_WAIT(n)  asm volatile("cp.async.wait_group %0;" :: "n"(n) : "memory")

// ---------------- init: LN(h0) -> g_hn; zero deg/cursor ----------------
__global__ void k_init_ln(const float* __restrict__ h,
                          const float* __restrict__ gam, const float* __restrict__ bet){
    int n = blockIdx.x*4 + (threadIdx.x>>5);
    if(n >= NPAD) return;
    int lane = threadIdx.x & 31;
    if(n < NN && lane == 0){ g_deg[n] = 0; g_cursor[n] = 0; }
    if(n >= NN){ ((float4*)g_hn)[n*32+lane] = make_float4(0.f,0.f,0.f,0.f); return; }
    float4 x = ((const float4*)h)[n*32 + lane];
    float s  = x.x+x.y+x.z+x.w;
    float ss = x.x*x.x+x.y*x.y+x.z*x.z+x.w*x.w;
    #pragma unroll
    for(int o=16;o;o>>=1){
        s  += __shfl_xor_sync(0xffffffffu, s,  o);
        ss += __shfl_xor_sync(0xffffffffu, ss, o);
    }
    float mean = s*(1.f/128.f);
    float var  = ss*(1.f/128.f) - mean*mean;
    float inv  = rsqrtf(var + 1e-5f);
    float4 g4 = ((const float4*)gam)[lane];
    float4 b4 = ((const float4*)bet)[lane];
    float4 y;
    y.x=(x.x-mean)*inv*g4.x+b4.x;
    y.y=(x.y-mean)*inv*g4.y+b4.y;
    y.z=(x.z-mean)*inv*g4.z+b4.z;
    y.w=(x.w-mean)*inv*g4.w+b4.w;
    ((float4*)g_hn)[n*32 + lane] = y;
}

// ---------------- combined prep ----------------
__global__ void k_prep_all(const float* Wq, const float* Wk, const float* Wv, const float* Ws,
                           const float* W1, const float* W2, const float* W3,
                           const float* __restrict__ pos, const float* __restrict__ ew,
                           const int* __restrict__ ei){
    int idx = blockIdx.x*256 + threadIdx.x;
    if(idx < 21*16384){
        int m = idx >> 14;
        int within = idx & 16383;
        int n = within >> 7, k2 = within & 127;
        int fam = m/3, layer = m - fam*3;
        const float* W;
        switch(fam){
            case 0: W = Wq; break; case 1: W = Wk; break; case 2: W = Wv; break;
            case 3: W = Ws; break; case 4: W = W1; break; case 5: W = W2; break;
            default: W = W3; break;
        }
        float w = W[layer*16384 + k2*128 + n];
        __nv_bfloat16 hi = __float2bfloat16(w);
        __nv_bfloat16 lo = __float2bfloat16(w - __bfloat162float(hi));
        char* base = g_wimg + (size_t)m*WMAT_B;
        int off = (n*WPAD + k2)*2;
        *(__nv_bfloat16*)(base + off) = hi;
        *(__nv_bfloat16*)(base + WIMG_B + off) = lo;
    }
    if(idx < NG*HID) g_pooled[idx] = 0.f;
    if(idx < NE){
        int e = idx;
        int s = ei[e], d = ei[NE+e];
        atomicAdd(&g_deg[d], 1);
        float dx = pos[d*3+0]-pos[s*3+0];
        float dy = pos[d*3+1]-pos[s*3+1];
        float dz = pos[d*3+2]-pos[s*3+2];
        float D  = sqrtf(dx*dx+dy*dy+dz*dz);
        float x  = D*0.1f;
        float cut = 0.f;
        if(x < 1.f){
            float x3=x*x*x, x4=x3*x, x5=x4*x;
            cut = 1.f - 6.f*x5 + 15.f*x4 - 10.f*x3;
        }
        float ed = expf(-D);
        const float cK = expf(-10.f);
        const float dc = (cK - 1.f)/8.f;
        float w = 4.5f/(1.f - cK); w = w*w;
        #pragma unroll
        for(int r=0;r<9;r++){
            float c = 1.f + (float)r*dc;
            float t = ed - c;
            g_efeat[e*EFS+r] = cut * expf(-w*t*t);
        }
        g_efeat[e*EFS+9]  = ew[e];
        g_efeat[e*EFS+10] = 0.f;
        g_efeat[e*EFS+11] = 0.f;
    }
}

// ---------------- shared GEMM pieces (256 threads, 8 warps: 4 M x 2 N; 64-row tiles) ----------------
__device__ __forceinline__ void stage_A64(char* smem, const float* __restrict__ A, int row0, int tid){
    const float4* A4 = (const float4*)A;
    #pragma unroll
    for(int j=0;j<8;j++){
        int idx = j*256 + tid;
        int row = idx >> 5;
        int c4  = (idx & 31) << 2;
        float4 a = A4[(size_t)(row0+row)*32 + (idx&31)];
        __nv_bfloat16 h0=__float2bfloat16(a.x), h1=__float2bfloat16(a.y);
        __nv_bfloat16 h2=__float2bfloat16(a.z), h3=__float2bfloat16(a.w);
        __nv_bfloat16 l0=__float2bfloat16(a.x-__bfloat162float(h0));
        __nv_bfloat16 l1=__float2bfloat16(a.y-__bfloat162float(h1));
        __nv_bfloat16 l2=__float2bfloat16(a.z-__bfloat162float(h2));
        __nv_bfloat16 l3=__float2bfloat16(a.w-__bfloat162float(h3));
        int off = (row*WPAD + c4)*2;
        *(__nv_bfloat162*)(smem + off  )           = __nv_bfloat162(h0,h1);
        *(__nv_bfloat162*)(smem + off+4)           = __nv_bfloat162(h2,h3);
        *(__nv_bfloat162*)(smem + A_IMG_B + off  ) = __nv_bfloat162(l0,l1);
        *(__nv_bfloat162*)(smem + A_IMG_B + off+4) = __nv_bfloat162(l2,l3);
    }
}
__device__ __forceinline__ void prefetch_W(uint32_t sbW, const char* __restrict__ wsrc, int tid){
    #pragma unroll
    for(int j=0;j<17;j++){
        int c = j*256 + tid;
        if(c < WMAT_B/16) cp16(sbW + c*16, wsrc + c*16);
    }
}
__device__ __forceinline__ void mma_tile64(uint32_t sbA, uint32_t sbW, float* acc, int wm, int wn, int lane){
    int i4 = lane>>3, r8 = lane&7;
    int a_row = wm*16 + r8 + (i4&1)*8;
    int a_col = (i4>>1)*8;
    int b_row = wn*64 + (i4>>1)*8 + r8;
    int b_col = (i4&1)*8;
    #pragma unroll
    for(int ks=0; ks<8; ks++){
        int k0 = ks*16;
        uint32_t aoff = (uint32_t)(a_row*WPAD + k0 + a_col)*2;
        uint32_t ahi[4], alo[4];
        ldsm4(sbA + aoff, ahi);
        ldsm4(sbA + A_IMG_B + aoff, alo);
        #pragma unroll
        for(int p=0;p<4;p++){
            uint32_t boff = (uint32_t)((b_row + p*16)*WPAD + k0 + b_col)*2;
            uint32_t bh[4], bl[4];
            ldsm4(sbW + boff, bh);
            ldsm4(sbW + WIMG_B + boff, bl);
            float* c0 = acc + p*8;
            float* c1 = acc + p*8 + 4;
            mma16816(c0, ahi, bh[0], bh[1]);
            mma16816(c1, ahi, bh[2], bh[3]);
            mma16816(c0, ahi, bl[0], bl[1]);
            mma16816(c1, ahi, bl[2], bl[3]);
            mma16816(c0, alo, bh[0], bh[1]);
            mma16816(c1, alo, bh[2], bh[3]);
        }
    }
}
__device__ __forceinline__ void epilogue_plain64(const float* acc, const float* __restrict__ bias,
                                                 float* __restrict__ out, int row0, int wm, int wn,
                                                 int lane){
    int rA = row0 + wm*16 + (lane>>2);
    int rB = rA + 8;
    #pragma unroll
    for(int f=0; f<8; f++){
        int idx = (f>>1)*8 + (f&1)*4;
        int col0 = wn*64 + f*8 + 2*(lane&3);
        float b0 = __ldg(bias + col0), b1 = __ldg(bias + col0 + 1);
        *(float2*)(out + (size_t)rA*HID + col0) = make_float2(acc[idx+0]+b0, acc[idx+1]+b1);
        *(float2*)(out + (size_t)rB*HID + col0) = make_float2(acc[idx+2]+b0, acc[idx+3]+b1);
    }
}
__device__ __forceinline__ void frag_to_img64(char* smem, const float* acc, const float* __restrict__ bias,
                                              int wm, int wn, int lane){
    int rA = wm*16 + (lane>>2);
    int rB = rA + 8;
    #pragma unroll
    for(int f=0; f<8; f++){
        int idx = (f>>1)*8 + (f&1)*4;
        int col0 = wn*64 + f*8 + 2*(lane&3);
        float b0 = __ldg(bias + col0), b1 = __ldg(bias + col0 + 1);
        float v0 = sp_f(acc[idx+0]+b0), v1 = sp_f(acc[idx+1]+b1);
        float v2 = sp_f(acc[idx+2]+b0), v3 = sp_f(acc[idx+3]+b1);
        __nv_bfloat16 h0=__float2bfloat16(v0), h1=__float2bfloat16(v1);
        __nv_bfloat16 h2=__float2bfloat16(v2), h3=__float2bfloat16(v3);
        __nv_bfloat16 l0=__float2bfloat16(v0-__bfloat162float(h0));
        __nv_bfloat16 l1=__float2bfloat16(v1-__bfloat162float(h1));
        __nv_bfloat16 l2=__float2bfloat16(v2-__bfloat162float(h2));
        __nv_bfloat16 l3=__float2bfloat16(v3-__bfloat162float(h3));
        int oA = (rA*WPAD + col0)*2, oB = (rB*WPAD + col0)*2;
        *(__nv_bfloat162*)(smem + oA)           = __nv_bfloat162(h0,h1);
        *(__nv_bfloat162*)(smem + A_IMG_B + oA) = __nv_bfloat162(l0,l1);
        *(__nv_bfloat162*)(smem + oB)           = __nv_bfloat162(h2,h3);
        *(__nv_bfloat162*)(smem + A_IMG_B + oB) = __nv_bfloat162(l2,l3);
    }
}

// ---------------- fused QKVS GEMM ----------------
__global__ void __launch_bounds__(256) k_gemm4(
        const float* __restrict__ A, const char* __restrict__ wimg, int layer,
        const float* __restrict__ bq, const float* __restrict__ bk,
        const float* __restrict__ bv, const float* __restrict__ bs,
        float* __restrict__ oq, float* __restrict__ ok,
        float* __restrict__ ov, float* __restrict__ oxr){
    extern __shared__ __align__(16) char smem[];
    uint32_t sb = smem_u32(smem);
    int tid = threadIdx.x, wid = tid>>5, lane = tid&31;
    int wm = wid & 3, wn = wid >> 2;
    int row0 = blockIdx.x*64;
    const uint32_t sbA = sb;
    const uint32_t sbW = sb + A_TOT_B;

    prefetch_W(sbW, wimg + (size_t)(0*3 + layer)*WMAT_B, tid);
    CP_COMMIT();
    stage_A64(smem, A, row0, tid);

    const float* biases[4] = {bq + layer*HID, bk + layer*HID, bv + layer*HID, bs + layer*HID};
    float* outs[4] = {oq, ok, ov, oxr};

    #pragma unroll
    for(int m=0;m<4;m++){
        CP_WAIT(0);
        __syncthreads();
        float acc[32];
        #pragma unroll
        for(int i=0;i<32;i++) acc[i]=0.f;
        mma_tile64(sbA, sbW, acc, wm, wn, lane);
        __syncthreads();
        if(m<3){
            prefetch_W(sbW, wimg + (size_t)((m+1)*3 + layer)*WMAT_B, tid);
            CP_COMMIT();
        }
        epilogue_plain64(acc, biases[m], outs[m], row0, wm, wn, lane);
    }
}

// ---------------- fused FFN ----------------
template<int MODE>
__global__ void __launch_bounds__(256) k_ffn(
        const char* __restrict__ wimg, int layer,
        const float* __restrict__ b1, const float* __restrict__ b2, const float* __restrict__ b3,
        const float* __restrict__ gam, const float* __restrict__ bet,
        const int* __restrict__ batch){
    extern __shared__ __align__(16) char smem[];
    uint32_t sb = smem_u32(smem);
    int tid = threadIdx.x, wid = tid>>5, lane = tid&31;
    int wm = wid & 3, wn = wid >> 2;
    int row0 = blockIdx.x*64;
    const uint32_t sbA = sb;
    const uint32_t sbW = sb + A_TOT_B;
    const float* bias1 = b1 + layer*HID;
    const float* bias2 = b2 + layer*HID;
    const float* bias3 = b3 + layer*HID;

    prefetch_W(sbW, wimg + (size_t)(4*3 + layer)*WMAT_B, tid);  // W1
    CP_COMMIT();
    stage_A64(smem, g_hn, row0, tid);
    CP_WAIT(0);
    __syncthreads();

    float acc[32];
    #pragma unroll
    for(int i=0;i<32;i++) acc[i]=0.f;
    mma_tile64(sbA, sbW, acc, wm, wn, lane);         // GEMM1
    __syncthreads();
    prefetch_W(sbW, wimg + (size_t)(5*3 + layer)*WMAT_B, tid);  // W2
    CP_COMMIT();
    frag_to_img64(smem, acc, bias1, wm, wn, lane);
    CP_WAIT(0);
    __syncthreads();

    #pragma unroll
    for(int i=0;i<32;i++) acc[i]=0.f;
    mma_tile64(sbA, sbW, acc, wm, wn, lane);         // GEMM2
    __syncthreads();
    prefetch_W(sbW, wimg + (size_t)(6*3 + layer)*WMAT_B, tid);  // W3
    CP_COMMIT();
    frag_to_img64(smem, acc, bias2, wm, wn, lane);
    CP_WAIT(0);
    __syncthreads();

    #pragma unroll
    for(int i=0;i<32;i++) acc[i]=0.f;
    mma_tile64(sbA, sbW, acc, wm, wn, lane);         // GEMM3
    __syncthreads();

    float* stage = (float*)smem;
    {
        int rA = wm*16 + (lane>>2);
        int rB = rA + 8;
        #pragma unroll
        for(int f=0; f<8; f++){
            int idx = (f>>1)*8 + (f&1)*4;
            int col0 = wn*64 + f*8 + 2*(lane&3);
            float b0 = __ldg(bias3 + col0), c1 = __ldg(bias3 + col0 + 1);
            float v0 = sp_f(acc[idx+0]+b0), v1 = sp_f(acc[idx+1]+c1);
            float v2 = sp_f(acc[idx+2]+b0), v3 = sp_f(acc[idx+3]+c1);
            const float2 r0 = *(const float2*)(g_hn + (size_t)(row0+rA)*HID + col0);
            const float2 r1 = *(const float2*)(g_hn + (size_t)(row0+rB)*HID + col0);
            stage[rA*129 + col0] = v0 + r0.x; stage[rA*129 + col0+1] = v1 + r0.y;
            stage[rB*129 + col0] = v2 + r1.x; stage[rB*129 + col0+1] = v3 + r1.y;
        }
    }
    __syncthreads();
    for(int r=wid; r<64; r+=8){
        float4 x;
        x.x = stage[r*129 + lane*4 + 0];
        x.y = stage[r*129 + lane*4 + 1];
        x.z = stage[r*129 + lane*4 + 2];
        x.w = stage[r*129 + lane*4 + 3];
        if(MODE == 1){
            float s  = x.x+x.y+x.z+x.w;
            float ss = x.x*x.x+x.y*x.y+x.z*x.z+x.w*x.w;
            #pragma unroll
            for(int o=16;o;o>>=1){
                s  += __shfl_xor_sync(0xffffffffu, s,  o);
                ss += __shfl_xor_sync(0xffffffffu, ss, o);
            }
            float mean = s*(1.f/128.f);
            float var  = ss*(1.f/128.f) - mean*mean;
            float inv  = rsqrtf(var + 1e-5f);
            float4 g4 = ((const float4*)gam)[lane];
            float4 b4 = ((const float4*)bet)[lane];
            float4 y;
            y.x=(x.x-mean)*inv*g4.x+b4.x;
            y.y=(x.y-mean)*inv*g4.y+b4.y;
            y.z=(x.z-mean)*inv*g4.z+b4.z;
            y.w=(x.w-mean)*inv*g4.w+b4.w;
            ((float4*)g_hn)[(size_t)(row0+r)*32 + lane] = y;
        } else {
            int gr = row0 + r;
            if(gr < NN){
                int g = batch[gr];
                float* base = &g_pooled[g*HID + 4*lane];
                atomicAdd(base+0, x.x); atomicAdd(base+1, x.y);
                atomicAdd(base+2, x.z); atomicAdd(base+3, x.w);
            }
        }
    }
}

// ---------------- CSR scan + scatter (+ CSR-order src/dst/efeat) ----------------
__global__ void k_scan(){
    __shared__ int wtot[32];
    __shared__ int carry;
    int tid = threadIdx.x, lane = tid & 31, wid = tid >> 5;
    if(tid==0) carry = 0;
    __syncthreads();
    for(int base=0; base<NN; base+=1024){
        int i = base + tid;
        int v = (i < NN) ? g_deg[i] : 0;
        int s = v;
        #pragma unroll
        for(int o=1;o<32;o<<=1){
            int t = __shfl_up_sync(0xffffffffu, s, o);
            if(lane >= o) s += t;
        }
        if(lane==31) wtot[wid] = s;
        __syncthreads();
        if(wid==0){
            int t = wtot[lane];
            int u = t;
            #pragma unroll
            for(int o=1;o<32;o<<=1){
                int tt = __shfl_up_sync(0xffffffffu, u, o);
                if(lane >= o) u += tt;
            }
            wtot[lane] = u;
        }
        __syncthreads();
        int off = carry + (wid>0 ? wtot[wid-1] : 0);
        if(i < NN) g_rowptr[i] = off + s - v;
        int tot = wtot[31];
        __syncthreads();
        if(tid==0) carry += tot;
        __syncthreads();
    }
    if(tid==0) g_rowptr[NN] = carry;
}
__global__ void k_scatter(const int* __restrict__ ei){
    int e = blockIdx.x*256 + threadIdx.x;
    if(e >= NE) return;
    int d = ei[NE+e];
    int p = g_rowptr[d] + atomicAdd(&g_cursor[d], 1);
    g_src[p] = ei[e];
    g_dst[p] = d;
    const float4* s4 = (const float4*)(g_efeat + (size_t)e*EFS);
    float4* d4 = (float4*)(g_efeat2 + (size_t)p*EFS);
    d4[0] = s4[0]; d4[1] = s4[1]; d4[2] = s4[2];
}

// ---------------- edge-parallel logits over CSR positions: all streams sequential ----------------
#define EPW 8
__global__ void __launch_bounds__(256) k_logits(const float* __restrict__ We){
    int p0 = (blockIdx.x*8 + (threadIdx.x>>5)) * EPW;
    if(p0 >= NE) return;
    int lane = threadIdx.x & 31;
    float4 w_e[10];
    #pragma unroll
    for(int r=0;r<10;r++) w_e[r] = __ldg(((const float4*)We) + r*32 + lane);
    int p1 = min(p0 + EPW, NE);
    for(int p=p0; p<p1; p++){
        int s = __ldg(&g_src[p]), d = __ldg(&g_dst[p]);
        float4 q4 = __ldg(((const float4*)g_q) + (size_t)d*32 + lane);
        float4 k4 = __ldg(((const float4*)g_k) + (size_t)s*32 + lane);
        float4 ef0 = __ldg((const float4*)(g_efeat2 + (size_t)p*EFS));
        float4 ef1 = __ldg((const float4*)(g_efeat2 + (size_t)p*EFS + 4));
        float2 ef2 = __ldg((const float2*)(g_efeat2 + (size_t)p*EFS + 8));
        float4 ea;
        ea.x = ef0.x*w_e[0].x + ef0.y*w_e[1].x + ef0.z*w_e[2].x + ef0.w*w_e[3].x
             + ef1.x*w_e[4].x + ef1.y*w_e[5].x + ef1.z*w_e[6].x + ef1.w*w_e[7].x
             + ef2.x*w_e[8].x + ef2.y*w_e[9].x;
        ea.y = ef0.x*w_e[0].y + ef0.y*w_e[1].y + ef0.z*w_e[2].y + ef0.w*w_e[3].y
             + ef1.x*w_e[4].y + ef1.y*w_e[5].y + ef1.z*w_e[6].y + ef1.w*w_e[7].y
             + ef2.x*w_e[8].y + ef2.y*w_e[9].y;
        ea.z = ef0.x*w_e[0].z + ef0.y*w_e[1].z + ef0.z*w_e[2].z + ef0.w*w_e[3].z
             + ef1.x*w_e[4].z + ef1.y*w_e[5].z + ef1.z*w_e[6].z + ef1.w*w_e[7].z
             + ef2.x*w_e[8].z + ef2.y*w_e[9].z;
        ea.w = ef0.x*w_e[0].w + ef0.y*w_e[1].w + ef0.z*w_e[2].w + ef0.w*w_e[3].w
             + ef1.x*w_e[4].w + ef1.y*w_e[5].w + ef1.z*w_e[6].w + ef1.w*w_e[7].w
             + ef2.x*w_e[8].w + ef2.y*w_e[9].w;
        float pq = q4.x*(k4.x+ea.x) + q4.y*(k4.y+ea.y) + q4.z*(k4.z+ea.z) + q4.w*(k4.w+ea.w);
        pq += __shfl_xor_sync(0xffffffffu, pq, 1);
        pq += __shfl_xor_sync(0xffffffffu, pq, 2);
        pq += __shfl_xor_sync(0xffffffffu, pq, 4);
        if((lane&7)==0) g_w[(size_t)p*4 + (lane>>3)] = pq * 0.17677669529663687f;
    }
}

// ---------------- node-parallel softmax+aggregate+gate+LN (CSR-sequential streams) ----------------
__global__ void __launch_bounds__(256) k_attn2(const float* __restrict__ We,
                       const float* __restrict__ Wb,
                       const float* __restrict__ gam, const float* __restrict__ bet){
    int n = blockIdx.x*8 + (threadIdx.x>>5);
    if(n >= NN) return;
    int lane = threadIdx.x & 31, head = lane>>3;
    int row = g_rowptr[n];
    int deg = g_rowptr[n+1] - row;

    float m = -1e30f;
    for(int i=0;i<deg;i++) m = fmaxf(m, __ldg(&g_w[(size_t)(row+i)*4 + head]));

    float4 accv = make_float4(0.f,0.f,0.f,0.f);
    float4 A0 = make_float4(0.f,0.f,0.f,0.f);
    float4 A1 = make_float4(0.f,0.f,0.f,0.f);
    float2 A2 = make_float2(0.f,0.f);
    float ssum = 0.f;
    for(int i=0;i<deg;i++){
        size_t p = row + i;
        int s = __ldg(&g_src[p]);
        float w = expf(__ldg(&g_w[p*4 + head]) - m);
        ssum += w;
        float4 v4 = __ldg(((const float4*)g_v) + (size_t)s*32 + lane);
        accv.x += w*v4.x; accv.y += w*v4.y; accv.z += w*v4.z; accv.w += w*v4.w;
        float4 ef0 = __ldg((const float4*)(g_efeat2 + p*EFS));
        float4 ef1 = __ldg((const float4*)(g_efeat2 + p*EFS + 4));
        float2 ef2 = __ldg((const float2*)(g_efeat2 + p*EFS + 8));
        A0.x += w*ef0.x; A0.y += w*ef0.y; A0.z += w*ef0.z; A0.w += w*ef0.w;
        A1.x += w*ef1.x; A1.y += w*ef1.y; A1.z += w*ef1.z; A1.w += w*ef1.w;
        A2.x += w*ef2.x; A2.y += w*ef2.y;
    }
    {
        float Ar[10] = {A0.x,A0.y,A0.z,A0.w,A1.x,A1.y,A1.z,A1.w,A2.x,A2.y};
        #pragma unroll
        for(int r=0;r<10;r++){
            float4 w4 = __ldg(((const float4*)We) + r*32 + lane);
            accv.x += Ar[r]*w4.x; accv.y += Ar[r]*w4.y;
            accv.z += Ar[r]*w4.z; accv.w += Ar[r]*w4.w;
        }
    }
    float inv = (deg>0) ? 1.f/ssum : 0.f;
    float4 o; o.x=accv.x*inv; o.y=accv.y*inv; o.z=accv.z*inv; o.w=accv.w*inv;

    float4 x  = ((const float4*)g_xr)[(size_t)n*32+lane];
    float4 hn = ((const float4*)g_hn)[(size_t)n*32+lane];
    float4 w0 = ((const float4*)Wb)[lane];
    float4 w1 = ((const float4*)Wb)[32+lane];
    float4 w2 = ((const float4*)Wb)[64+lane];
    float p = o.x*w0.x + o.y*w0.y + o.z*w0.z + o.w*w0.w
            + x.x*w1.x + x.y*w1.y + x.z*w1.z + x.w*w1.w
            + (o.x-x.x)*w2.x + (o.y-x.y)*w2.y + (o.z-x.z)*w2.z + (o.w-x.w)*w2.w;
    #pragma unroll
    for(int off=16;off;off>>=1) p += __shfl_xor_sync(0xffffffffu, p, off);
    float beta = 1.f/(1.f+expf(-p));
    float4 r;
    r.x = beta*x.x + (1.f-beta)*o.x;
    r.y = beta*x.y + (1.f-beta)*o.y;
    r.z = beta*x.z + (1.f-beta)*o.z;
    r.w = beta*x.w + (1.f-beta)*o.w;
    float4 hv;
    hv.x = hn.x + sp_f(r.x); hv.y = hn.y + sp_f(r.y);
    hv.z = hn.z + sp_f(r.z); hv.w = hn.w + sp_f(r.w);

    float s  = hv.x+hv.y+hv.z+hv.w;
    float ss = hv.x*hv.x+hv.y*hv.y+hv.z*hv.z+hv.w*hv.w;
    #pragma unroll
    for(int off=16;off;off>>=1){
        s  += __shfl_xor_sync(0xffffffffu, s,  off);
        ss += __shfl_xor_sync(0xffffffffu, ss, off);
    }
    float mean = s*(1.f/128.f);
    float var  = ss*(1.f/128.f) - mean*mean;
    float invs = rsqrtf(var + 1e-5f);
    float4 g4 = ((const float4*)gam)[lane];
    float4 b4 = ((const float4*)bet)[lane];
    float4 y;
    y.x=(hv.x-mean)*invs*g4.x+b4.x;
    y.y=(hv.y-mean)*invs*g4.y+b4.y;
    y.z=(hv.z-mean)*invs*g4.z+b4.z;
    y.w=(hv.w-mean)*invs*g4.w+b4.w;
    ((float4*)g_hn)[(size_t)n*32+lane] = y;
}

// ---------------- readout head ----------------
__global__ void k_final(const float* __restrict__ Wo1, const float* __restrict__ bo1,
                        const float* __restrict__ Wo2, const float* __restrict__ bo2,
                        float* __restrict__ out){
    int g = blockIdx.x*4 + (threadIdx.x>>5);
    if(g >= NG) return;
    int lane = threadIdx.x & 31;
    float4 acc = ((const float4*)bo1)[lane];
    const float* p = &g_pooled[g*HID];
    for(int k2=0;k2<HID;k2++){
        float a = p[k2];
        float4 w = __ldg(((const float4*)Wo1) + k2*32 + lane);
        acc.x += a*w.x; acc.y += a*w.y; acc.z += a*w.z; acc.w += a*w.w;
    }
    float4 w2 = ((const float4*)Wo2)[lane];
    float r = sp_f(acc.x)*w2.x + sp_f(acc.y)*w2.y + sp_f(acc.z)*w2.z + sp_f(acc.w)*w2.w;
    #pragma unroll
    for(int off=16;off;off>>=1) r += __shfl_xor_sync(0xffffffffu, r, off);
    if(lane==0) out[g] = r + bo2[0];
}

// ---------------- driver ----------------
extern "C" void kernel_launch(void* const* d_in, const int* in_sizes, int n_in,
                              void* d_out, int out_size){
    const float* h   = (const float*)d_in[0];
    const float* pos = (const float*)d_in[1];
    const float* ew  = (const float*)d_in[2];
    const float* Wq  = (const float*)d_in[3];  const float* bq = (const float*)d_in[4];
    const float* Wk  = (const float*)d_in[5];  const float* bk = (const float*)d_in[6];
    const float* Wv  = (const float*)d_in[7];  const float* bv = (const float*)d_in[8];
    const float* We  = (const float*)d_in[9];
    const float* Ws  = (const float*)d_in[10]; const float* bs = (const float*)d_in[11];
    const float* Wb  = (const float*)d_in[12];
    const float* W1  = (const float*)d_in[13]; const float* b1 = (const float*)d_in[14];
    const float* W2  = (const float*)d_in[15]; const float* b2 = (const float*)d_in[16];
    const float* W3  = (const float*)d_in[17]; const float* b3 = (const float*)d_in[18];
    const float* lgm = (const float*)d_in[19]; const float* lbt = (const float*)d_in[20];
    const float* Wo1 = (const float*)d_in[21]; const float* bo1 = (const float*)d_in[22];
    const float* Wo2 = (const float*)d_in[23]; const float* bo2 = (const float*)d_in[24];
    const int*   ei  = (const int*)d_in[25];
    const int*   bat = (const int*)d_in[26];
    float* out = (float*)d_out;

    float *p_hn,*p_q,*p_k,*p_v,*p_xr;
    char* p_wimg;
    cudaGetSymbolAddress((void**)&p_hn, g_hn);
    cudaGetSymbolAddress((void**)&p_q,  g_q);
    cudaGetSymbolAddress((void**)&p_k,  g_k);
    cudaGetSymbolAddress((void**)&p_v,  g_v);
    cudaGetSymbolAddress((void**)&p_xr, g_xr);
    cudaGetSymbolAddress((void**)&p_wimg, g_wimg);

    cudaFuncSetAttribute(k_gemm4,   cudaFuncAttributeMaxDynamicSharedMemorySize, SMB);
    cudaFuncSetAttribute(k_ffn<1>,  cudaFuncAttributeMaxDynamicSharedMemorySize, SMB);
    cudaFuncSetAttribute(k_ffn<2>,  cudaFuncAttributeMaxDynamicSharedMemorySize, SMB);

    const int NB = NPAD/64; // 782

    k_init_ln <<<NPAD/4, 128>>>(h, lgm, lbt);                                    // 0
    k_prep_all<<<(NE+255)/256, 256>>>(Wq,Wk,Wv,Ws,W1,W2,W3, pos, ew, ei);        // 1
    k_scan    <<<1, 1024>>>();                                                   // 2
    k_gemm4   <<<NB, 256, SMB>>>(p_hn, p_wimg, 0, bq, bk, bv, bs,                // 3 <- profiled
                                 p_q, p_k, p_v, p_xr);
    k_scatter <<<(NE+255)/256, 256>>>(ei);                                       // 4

    for(int i=0;i<NLAY;i++){
        const float* Wei=We+i*10*HID;
        const float* Wbi=Wb+i*3*HID;
        if(i>0)
            k_gemm4 <<<NB, 256, SMB>>>(p_hn, p_wimg, i, bq, bk, bv, bs, p_q, p_k, p_v, p_xr);
        k_logits<<<(NE/EPW+7)/8, 256>>>(Wei);
        k_attn2 <<<(NN+7)/8, 256>>>(Wei, Wbi, lgm, lbt);
        if(i < NLAY-1)
            k_ffn<1><<<NB, 256, SMB>>>(p_wimg, i, b1, b2, b3, lgm, lbt, nullptr);
        else
            k_ffn<2><<<NB, 256, SMB>>>(p_wimg, i, b1, b2, b3, nullptr, nullptr, bat);
    }

    k_final<<<NG/4, 128>>>(Wo1, bo1, Wo2, bo2, out);
}